// round 3
// baseline (speedup 1.0000x reference)
#include <cuda_runtime.h>
#include <cstdint>

#define NN  40000
#define EE  640000
#define NNZ (EE + NN)   // 680000 (edges + self-loops)

typedef unsigned long long ull;

// ---------------- scratch (device globals — no runtime allocation) ----------
__device__ __align__(256) float g_buf0[NN * 128];
__device__ __align__(256) float g_buf1[NN * 128];
__device__ float g_dinv[NN];
__device__ int   g_deg[NN];
__device__ int   g_rowptr[NN + 1];
__device__ int   g_cursor[NN];
__device__ int   g_col[NNZ];
__device__ float g_ew[NNZ];

// ---------------- packed fp32x2 helpers (sm_10x) -----------------------------
__device__ __forceinline__ ull ffma2(ull a, ull b, ull c) {
  ull d;
  asm("fma.rn.f32x2 %0, %1, %2, %3;" : "=l"(d) : "l"(a), "l"(b), "l"(c));
  return d;
}
__device__ __forceinline__ float hsum2(ull v) {
  float lo, hi;
  asm("mov.b64 {%0, %1}, %2;" : "=f"(lo), "=f"(hi) : "l"(v));
  return lo + hi;
}

// ---------------- preprocessing ---------------------------------------------
__global__ void init_deg_kernel() {
  int i = blockIdx.x * 256 + threadIdx.x;
  if (i < NN) g_deg[i] = 0;
}

__global__ void count_deg_kernel(const int* __restrict__ dst) {
  int e = blockIdx.x * 256 + threadIdx.x;
  if (e < EE) atomicAdd(&g_deg[dst[e]], 1);
}

__global__ void calc_dinv_kernel() {
  int i = blockIdx.x * 256 + threadIdx.x;
  if (i < NN) g_dinv[i] = rsqrtf((float)(g_deg[i] + 1));  // +1 self-loop; deg>=1
}

// Single-block exclusive scan of (deg[i]+1) -> rowptr; cursor = rowptr copy.
__global__ void __launch_bounds__(1024) scan_kernel() {
  __shared__ int sh[1024];
  const int t = threadIdx.x;
  const int CH = (NN + 1023) / 1024;  // 40
  const int base = t * CH;
  int s = 0;
  for (int i = 0; i < CH; i++) {
    int idx = base + i;
    if (idx < NN) s += g_deg[idx] + 1;
  }
  sh[t] = s;
  __syncthreads();
  for (int off = 1; off < 1024; off <<= 1) {
    int v = (t >= off) ? sh[t - off] : 0;
    __syncthreads();
    sh[t] += v;
    __syncthreads();
  }
  int run = (t == 0) ? 0 : sh[t - 1];
  for (int i = 0; i < CH; i++) {
    int idx = base + i;
    if (idx < NN) {
      g_rowptr[idx] = run;
      g_cursor[idx] = run;
      run += g_deg[idx] + 1;
    }
  }
  if (t == 1023) g_rowptr[NN] = sh[1023];  // == NNZ
}

__global__ void fill_csr_kernel(const int* __restrict__ src,
                                const int* __restrict__ dst) {
  int t = blockIdx.x * 256 + threadIdx.x;
  if (t < EE) {
    int s = src[t], d = dst[t];
    int pos = atomicAdd(&g_cursor[d], 1);
    g_col[pos] = s;
    g_ew[pos] = g_dinv[s] * g_dinv[d];
  } else if (t < EE + NN) {
    int i = t - EE;
    int pos = atomicAdd(&g_cursor[i], 1);
    g_col[pos] = i;
    float di = g_dinv[i];
    g_ew[pos] = di * di;
  }
}

// ---------------- dense: out[N,DOUT] = A[N,K] @ W[K,DOUT] (+bias)(relu) -----
// One warp computes R=8 rows; lanes cover a 64-wide (or 32-wide) column tile.
// Inner product packed over k-pairs via fma.rn.f32x2 (W staged transposed in
// shared, padded +4 words: 16B-aligned & conflict-free for LDS.128).
template <int K, int DOUT, bool RELU, bool BIAS>
__global__ void __launch_bounds__(256) gemm_kernel(
    const float* __restrict__ A, const float* __restrict__ W,
    const float* __restrict__ bias, float* __restrict__ out) {
  constexpr int COLT = (DOUT < 64) ? DOUT : 64;
  constexpr int VPT = COLT / 32;   // 1 or 2
  constexpr int KS = K + 4;        // padded stride (words)
  constexpr int R = 8;
  __shared__ __align__(16) float Ws[COLT * KS];

  const int col0 = blockIdx.y * COLT;
  for (int i = threadIdx.x; i < COLT * K; i += 256) {
    int c = i / K, k = i - c * K;
    Ws[c * KS + k] = W[k * DOUT + col0 + c];
  }
  __syncthreads();

  const int lane = threadIdx.x & 31;
  const int row0 = (blockIdx.x * 8 + (threadIdx.x >> 5)) * R;

  ull acc[R][VPT];
#pragma unroll
  for (int r = 0; r < R; r++)
#pragma unroll
    for (int v = 0; v < VPT; v++) acc[r][v] = 0ull;

  const float* a_base = A + (size_t)row0 * K;
#pragma unroll 2
  for (int k = 0; k < K; k += 4) {
    ull w01[VPT], w23[VPT];
#pragma unroll
    for (int v = 0; v < VPT; v++) {
      float4 wv = *reinterpret_cast<const float4*>(&Ws[(lane + 32 * v) * KS + k]);
      w01[v] = reinterpret_cast<ull*>(&wv)[0];
      w23[v] = reinterpret_cast<ull*>(&wv)[1];
    }
#pragma unroll
    for (int r = 0; r < R; r++) {
      float4 av = __ldg(reinterpret_cast<const float4*>(a_base + r * K + k));
      ull a01 = reinterpret_cast<ull*>(&av)[0];
      ull a23 = reinterpret_cast<ull*>(&av)[1];
#pragma unroll
      for (int v = 0; v < VPT; v++) {
        acc[r][v] = ffma2(a01, w01[v], acc[r][v]);
        acc[r][v] = ffma2(a23, w23[v], acc[r][v]);
      }
    }
  }

#pragma unroll
  for (int r = 0; r < R; r++) {
#pragma unroll
    for (int v = 0; v < VPT; v++) {
      float s = hsum2(acc[r][v]);
      int c = col0 + lane + 32 * v;
      if (BIAS) s += __ldg(&bias[c]);
      if (RELU) s = fmaxf(s, 0.0f);
      out[(size_t)(row0 + r) * DOUT + c] = s;
    }
  }
}

// ---------------- aggregation: Hout[i] = sum_{e in row i} ew[e]*Hin[col[e]] --
// One warp per node, gather-only (no atomics), float4/float2 vector loads.
template <int D, bool RELU, bool BIAS>
__global__ void __launch_bounds__(256) agg_kernel(
    const float* __restrict__ Hin, const float* __restrict__ bias,
    float* __restrict__ Hout) {
  const int node = blockIdx.x * 8 + (threadIdx.x >> 5);
  const int lane = threadIdx.x & 31;
  const int beg = g_rowptr[node];
  const int end = g_rowptr[node + 1];

  if constexpr (D == 128) {
    float4 acc = make_float4(0.f, 0.f, 0.f, 0.f);
    int e = beg;
    for (; e + 2 <= end; e += 2) {
      int c0 = __ldg(&g_col[e]);
      int c1 = __ldg(&g_col[e + 1]);
      float w0 = __ldg(&g_ew[e]);
      float w1 = __ldg(&g_ew[e + 1]);
      float4 x0 = __ldg(reinterpret_cast<const float4*>(Hin + (size_t)c0 * D) + lane);
      float4 x1 = __ldg(reinterpret_cast<const float4*>(Hin + (size_t)c1 * D) + lane);
      acc.x += w0 * x0.x; acc.y += w0 * x0.y; acc.z += w0 * x0.z; acc.w += w0 * x0.w;
      acc.x += w1 * x1.x; acc.y += w1 * x1.y; acc.z += w1 * x1.z; acc.w += w1 * x1.w;
    }
    if (e < end) {
      int c0 = __ldg(&g_col[e]);
      float w0 = __ldg(&g_ew[e]);
      float4 x0 = __ldg(reinterpret_cast<const float4*>(Hin + (size_t)c0 * D) + lane);
      acc.x += w0 * x0.x; acc.y += w0 * x0.y; acc.z += w0 * x0.z; acc.w += w0 * x0.w;
    }
    if (BIAS) {
      float4 b = __ldg(reinterpret_cast<const float4*>(bias) + lane);
      acc.x += b.x; acc.y += b.y; acc.z += b.z; acc.w += b.w;
    }
    if (RELU) {
      acc.x = fmaxf(acc.x, 0.f); acc.y = fmaxf(acc.y, 0.f);
      acc.z = fmaxf(acc.z, 0.f); acc.w = fmaxf(acc.w, 0.f);
    }
    reinterpret_cast<float4*>(Hout + (size_t)node * D)[lane] = acc;
  } else {  // D == 64
    float2 acc = make_float2(0.f, 0.f);
    int e = beg;
    for (; e + 2 <= end; e += 2) {
      int c0 = __ldg(&g_col[e]);
      int c1 = __ldg(&g_col[e + 1]);
      float w0 = __ldg(&g_ew[e]);
      float w1 = __ldg(&g_ew[e + 1]);
      float2 x0 = __ldg(reinterpret_cast<const float2*>(Hin + (size_t)c0 * D) + lane);
      float2 x1 = __ldg(reinterpret_cast<const float2*>(Hin + (size_t)c1 * D) + lane);
      acc.x += w0 * x0.x; acc.y += w0 * x0.y;
      acc.x += w1 * x1.x; acc.y += w1 * x1.y;
    }
    if (e < end) {
      int c0 = __ldg(&g_col[e]);
      float w0 = __ldg(&g_ew[e]);
      float2 x0 = __ldg(reinterpret_cast<const float2*>(Hin + (size_t)c0 * D) + lane);
      acc.x += w0 * x0.x; acc.y += w0 * x0.y;
    }
    if (BIAS) {
      float2 b = __ldg(reinterpret_cast<const float2*>(bias) + lane);
      acc.x += b.x; acc.y += b.y;
    }
    if (RELU) { acc.x = fmaxf(acc.x, 0.f); acc.y = fmaxf(acc.y, 0.f); }
    reinterpret_cast<float2*>(Hout + (size_t)node * D)[lane] = acc;
  }
}

// ---------------- launch ------------------------------------------------------
extern "C" void kernel_launch(void* const* d_in, const int* in_sizes, int n_in,
                              void* d_out, int out_size) {
  (void)in_sizes; (void)n_in; (void)out_size;
  const float* x  = (const float*)d_in[0];
  const int*   ei = (const int*)d_in[1];
  const int* src = ei;
  const int* dst = ei + EE;
  const float* W1 = (const float*)d_in[3];
  const float* b1 = (const float*)d_in[4];
  const float* W2 = (const float*)d_in[5];
  const float* b2 = (const float*)d_in[6];
  const float* W3 = (const float*)d_in[7];
  const float* b3 = (const float*)d_in[8];
  const float* W4 = (const float*)d_in[9];
  const float* b4 = (const float*)d_in[10];
  const float* Wl = (const float*)d_in[11];
  const float* bl = (const float*)d_in[12];
  float* out = (float*)d_out;

  float *buf0, *buf1;
  cudaGetSymbolAddress((void**)&buf0, g_buf0);
  cudaGetSymbolAddress((void**)&buf1, g_buf1);

  // ---- GCN normalization + CSR build (over dst, incl. self-loops) ----
  init_deg_kernel<<<(NN + 255) / 256, 256>>>();
  count_deg_kernel<<<(EE + 255) / 256, 256>>>(dst);
  calc_dinv_kernel<<<(NN + 255) / 256, 256>>>();
  scan_kernel<<<1, 1024>>>();
  fill_csr_kernel<<<(EE + NN + 255) / 256, 256>>>(src, dst);

  const int GEMM_BLOCKS = NN / 64;  // 625 (8 warps x 8 rows per block)
  const int AGG_BLOCKS = NN / 8;    // 5000 (8 warps per block)

  // L1: t = x @ W1 ; h1 = relu(agg(t) + b1)
  gemm_kernel<128, 64, false, false><<<dim3(GEMM_BLOCKS, 1), 256>>>(x, W1, nullptr, buf0);
  agg_kernel<64, true, true><<<AGG_BLOCKS, 256>>>(buf0, b1, buf1);
  // L2 (agg-first, d_in < d_out): a = agg(h1) ; h2 = relu(a @ W2 + b2)
  agg_kernel<64, false, false><<<AGG_BLOCKS, 256>>>(buf1, nullptr, buf0);
  gemm_kernel<64, 128, true, true><<<dim3(GEMM_BLOCKS, 2), 256>>>(buf0, W2, b2, buf1);
  // L3: t = h2 @ W3 ; h3 = relu(agg(t) + b3)
  gemm_kernel<128, 128, false, false><<<dim3(GEMM_BLOCKS, 2), 256>>>(buf1, W3, nullptr, buf0);
  agg_kernel<128, true, true><<<AGG_BLOCKS, 256>>>(buf0, b3, buf1);
  // L4: t = h3 @ W4 ; h4 = relu(agg(t) + b4)
  gemm_kernel<128, 64, false, false><<<dim3(GEMM_BLOCKS, 1), 256>>>(buf1, W4, nullptr, buf0);
  agg_kernel<64, true, true><<<AGG_BLOCKS, 256>>>(buf0, b4, buf1);
  // Head: out = h4 @ Wl + bl
  gemm_kernel<64, 32, false, true><<<dim3(GEMM_BLOCKS, 1), 256>>>(buf1, Wl, bl, out);
}

// round 4
// speedup vs baseline: 1.1862x; 1.1862x over previous
#include <cuda_runtime.h>
#include <cstdint>

#define NN  40000
#define EE  640000
#define NNZ (EE + NN)   // 680000 (edges + self-loops)

#define NSCAN_BLK 40    // 40 blocks x 1000 elements = NN
#define SCAN_CH   1000

typedef unsigned long long ull;

// ---------------- scratch (device globals — no runtime allocation) ----------
__device__ __align__(256) float g_buf0[NN * 128];
__device__ __align__(256) float g_buf1[NN * 128];
__device__ float g_dinv[NN];
__device__ int   g_deg[NN];
__device__ int   g_rowptr[NN + 1];
__device__ int   g_cursor[NN];
__device__ __align__(16) int2 g_adj[NNZ];   // {col, bitcast(weight)}
__device__ int   g_blocksum[NSCAN_BLK];
__device__ int   g_blockoff[NSCAN_BLK];

// ---------------- packed fp32x2 helpers (sm_10x) -----------------------------
__device__ __forceinline__ ull ffma2(ull a, ull b, ull c) {
  ull d;
  asm("fma.rn.f32x2 %0, %1, %2, %3;" : "=l"(d) : "l"(a), "l"(b), "l"(c));
  return d;
}
__device__ __forceinline__ float hsum2(ull v) {
  float lo, hi;
  asm("mov.b64 {%0, %1}, %2;" : "=f"(lo), "=f"(hi) : "l"(v));
  return lo + hi;
}

// ---------------- preprocessing ---------------------------------------------
__global__ void init_deg_kernel() {
  int i = blockIdx.x * 256 + threadIdx.x;
  if (i < NN) g_deg[i] = 0;
}

__global__ void count_deg_kernel(const int* __restrict__ dst) {
  int e = blockIdx.x * 256 + threadIdx.x;
  if (e < EE) atomicAdd(&g_deg[dst[e]], 1);
}

// Per-block sums of (deg+1) over SCAN_CH-chunks; also computes dinv.
__global__ void __launch_bounds__(256) block_sums_kernel() {
  __shared__ int sh[8];
  const int b = blockIdx.x, t = threadIdx.x;
  int s = 0;
  for (int i = t; i < SCAN_CH; i += 256) {
    int idx = b * SCAN_CH + i;
    int d1 = g_deg[idx] + 1;
    s += d1;
    g_dinv[idx] = rsqrtf((float)d1);
  }
#pragma unroll
  for (int off = 16; off > 0; off >>= 1) s += __shfl_down_sync(0xffffffffu, s, off);
  if ((t & 31) == 0) sh[t >> 5] = s;
  __syncthreads();
  if (t < 8) {
    s = sh[t];
#pragma unroll
    for (int off = 4; off > 0; off >>= 1) s += __shfl_down_sync(0xffu, s, off);
    if (t == 0) g_blocksum[b] = s;
  }
}

// Exclusive scan of the NSCAN_BLK block sums (single warp-ish block).
__global__ void scan_offsets_kernel() {
  __shared__ int sh[64];
  const int t = threadIdx.x;
  sh[t] = (t < NSCAN_BLK) ? g_blocksum[t] : 0;
  __syncthreads();
  for (int off = 1; off < 64; off <<= 1) {
    int v = (t >= off) ? sh[t - off] : 0;
    __syncthreads();
    sh[t] += v;
    __syncthreads();
  }
  if (t < NSCAN_BLK) g_blockoff[t] = (t == 0) ? 0 : sh[t - 1];
}

// Block-local scan + global offset -> rowptr/cursor.
__global__ void __launch_bounds__(1024) scan_write_kernel() {
  __shared__ int sh[1024];
  const int b = blockIdx.x, t = threadIdx.x;
  const int idx = b * SCAN_CH + t;
  int v = (t < SCAN_CH) ? g_deg[idx] + 1 : 0;
  sh[t] = v;
  __syncthreads();
  for (int off = 1; off < 1024; off <<= 1) {
    int u = (t >= off) ? sh[t - off] : 0;
    __syncthreads();
    sh[t] += u;
    __syncthreads();
  }
  const int base = g_blockoff[b];
  if (t < SCAN_CH) {
    int p = base + ((t == 0) ? 0 : sh[t - 1]);
    g_rowptr[idx] = p;
    g_cursor[idx] = p;
  }
  if (b == NSCAN_BLK - 1 && t == SCAN_CH - 1) g_rowptr[NN] = base + sh[t];
}

__global__ void fill_csr_kernel(const int* __restrict__ src,
                                const int* __restrict__ dst) {
  int t = blockIdx.x * 256 + threadIdx.x;
  if (t < EE) {
    int s = src[t], d = dst[t];
    int pos = atomicAdd(&g_cursor[d], 1);
    g_adj[pos] = make_int2(s, __float_as_int(g_dinv[s] * g_dinv[d]));
  } else if (t < NNZ) {
    int i = t - EE;
    int pos = atomicAdd(&g_cursor[i], 1);
    float di = g_dinv[i];
    g_adj[pos] = make_int2(i, __float_as_int(di * di));
  }
}

// ---------------- dense: out[N,DOUT] = A[N,K] @ W[K,DOUT] (+bias)(relu) -----
template <int K, int DOUT, bool RELU, bool BIAS>
__global__ void __launch_bounds__(256) gemm_kernel(
    const float* __restrict__ A, const float* __restrict__ W,
    const float* __restrict__ bias, float* __restrict__ out) {
  constexpr int COLT = (DOUT < 64) ? DOUT : 64;
  constexpr int VPT = COLT / 32;   // 1 or 2
  constexpr int KS = K + 4;        // padded stride (words)
  constexpr int R = 8;
  __shared__ __align__(16) float Ws[COLT * KS];

  const int col0 = blockIdx.y * COLT;
  for (int i = threadIdx.x; i < COLT * K; i += 256) {
    int c = i / K, k = i - c * K;
    Ws[c * KS + k] = W[k * DOUT + col0 + c];
  }
  __syncthreads();

  const int lane = threadIdx.x & 31;
  const int row0 = (blockIdx.x * 8 + (threadIdx.x >> 5)) * R;

  ull acc[R][VPT];
#pragma unroll
  for (int r = 0; r < R; r++)
#pragma unroll
    for (int v = 0; v < VPT; v++) acc[r][v] = 0ull;

  const float* a_base = A + (size_t)row0 * K;
#pragma unroll 2
  for (int k = 0; k < K; k += 4) {
    ull w01[VPT], w23[VPT];
#pragma unroll
    for (int v = 0; v < VPT; v++) {
      float4 wv = *reinterpret_cast<const float4*>(&Ws[(lane + 32 * v) * KS + k]);
      w01[v] = reinterpret_cast<ull*>(&wv)[0];
      w23[v] = reinterpret_cast<ull*>(&wv)[1];
    }
#pragma unroll
    for (int r = 0; r < R; r++) {
      float4 av = __ldg(reinterpret_cast<const float4*>(a_base + r * K + k));
      ull a01 = reinterpret_cast<ull*>(&av)[0];
      ull a23 = reinterpret_cast<ull*>(&av)[1];
#pragma unroll
      for (int v = 0; v < VPT; v++) {
        acc[r][v] = ffma2(a01, w01[v], acc[r][v]);
        acc[r][v] = ffma2(a23, w23[v], acc[r][v]);
      }
    }
  }

#pragma unroll
  for (int r = 0; r < R; r++) {
#pragma unroll
    for (int v = 0; v < VPT; v++) {
      float s = hsum2(acc[r][v]);
      int c = col0 + lane + 32 * v;
      if (BIAS) s += __ldg(&bias[c]);
      if (RELU) s = fmaxf(s, 0.0f);
      out[(size_t)(row0 + r) * DOUT + c] = s;
    }
  }
}

// ---------------- aggregation: Hout[i] = sum_{e in row i} w[e]*Hin[col[e]] --
// One warp per node, gather-only, packed {col,w} adjacency, unroll x4.
template <int D, bool RELU, bool BIAS>
__global__ void __launch_bounds__(256) agg_kernel(
    const float* __restrict__ Hin, const float* __restrict__ bias,
    float* __restrict__ Hout) {
  const int node = blockIdx.x * 8 + (threadIdx.x >> 5);
  const int lane = threadIdx.x & 31;
  const int beg = g_rowptr[node];
  const int end = g_rowptr[node + 1];

  if constexpr (D == 128) {
    float4 acc = make_float4(0.f, 0.f, 0.f, 0.f);
    int e = beg;
    for (; e + 4 <= end; e += 4) {
      int2 a0 = __ldg(&g_adj[e + 0]);
      int2 a1 = __ldg(&g_adj[e + 1]);
      int2 a2 = __ldg(&g_adj[e + 2]);
      int2 a3 = __ldg(&g_adj[e + 3]);
      float4 x0 = __ldg(reinterpret_cast<const float4*>(Hin + (size_t)a0.x * D) + lane);
      float4 x1 = __ldg(reinterpret_cast<const float4*>(Hin + (size_t)a1.x * D) + lane);
      float4 x2 = __ldg(reinterpret_cast<const float4*>(Hin + (size_t)a2.x * D) + lane);
      float4 x3 = __ldg(reinterpret_cast<const float4*>(Hin + (size_t)a3.x * D) + lane);
      float w0 = __int_as_float(a0.y), w1 = __int_as_float(a1.y);
      float w2 = __int_as_float(a2.y), w3 = __int_as_float(a3.y);
      acc.x += w0 * x0.x; acc.y += w0 * x0.y; acc.z += w0 * x0.z; acc.w += w0 * x0.w;
      acc.x += w1 * x1.x; acc.y += w1 * x1.y; acc.z += w1 * x1.z; acc.w += w1 * x1.w;
      acc.x += w2 * x2.x; acc.y += w2 * x2.y; acc.z += w2 * x2.z; acc.w += w2 * x2.w;
      acc.x += w3 * x3.x; acc.y += w3 * x3.y; acc.z += w3 * x3.z; acc.w += w3 * x3.w;
    }
    for (; e < end; e++) {
      int2 a0 = __ldg(&g_adj[e]);
      float w0 = __int_as_float(a0.y);
      float4 x0 = __ldg(reinterpret_cast<const float4*>(Hin + (size_t)a0.x * D) + lane);
      acc.x += w0 * x0.x; acc.y += w0 * x0.y; acc.z += w0 * x0.z; acc.w += w0 * x0.w;
    }
    if (BIAS) {
      float4 b = __ldg(reinterpret_cast<const float4*>(bias) + lane);
      acc.x += b.x; acc.y += b.y; acc.z += b.z; acc.w += b.w;
    }
    if (RELU) {
      acc.x = fmaxf(acc.x, 0.f); acc.y = fmaxf(acc.y, 0.f);
      acc.z = fmaxf(acc.z, 0.f); acc.w = fmaxf(acc.w, 0.f);
    }
    reinterpret_cast<float4*>(Hout + (size_t)node * D)[lane] = acc;
  } else {  // D == 64
    float2 acc = make_float2(0.f, 0.f);
    int e = beg;
    for (; e + 4 <= end; e += 4) {
      int2 a0 = __ldg(&g_adj[e + 0]);
      int2 a1 = __ldg(&g_adj[e + 1]);
      int2 a2 = __ldg(&g_adj[e + 2]);
      int2 a3 = __ldg(&g_adj[e + 3]);
      float2 x0 = __ldg(reinterpret_cast<const float2*>(Hin + (size_t)a0.x * D) + lane);
      float2 x1 = __ldg(reinterpret_cast<const float2*>(Hin + (size_t)a1.x * D) + lane);
      float2 x2 = __ldg(reinterpret_cast<const float2*>(Hin + (size_t)a2.x * D) + lane);
      float2 x3 = __ldg(reinterpret_cast<const float2*>(Hin + (size_t)a3.x * D) + lane);
      float w0 = __int_as_float(a0.y), w1 = __int_as_float(a1.y);
      float w2 = __int_as_float(a2.y), w3 = __int_as_float(a3.y);
      acc.x += w0 * x0.x; acc.y += w0 * x0.y;
      acc.x += w1 * x1.x; acc.y += w1 * x1.y;
      acc.x += w2 * x2.x; acc.y += w2 * x2.y;
      acc.x += w3 * x3.x; acc.y += w3 * x3.y;
    }
    for (; e < end; e++) {
      int2 a0 = __ldg(&g_adj[e]);
      float w0 = __int_as_float(a0.y);
      float2 x0 = __ldg(reinterpret_cast<const float2*>(Hin + (size_t)a0.x * D) + lane);
      acc.x += w0 * x0.x; acc.y += w0 * x0.y;
    }
    if (BIAS) {
      float2 b = __ldg(reinterpret_cast<const float2*>(bias) + lane);
      acc.x += b.x; acc.y += b.y;
    }
    if (RELU) { acc.x = fmaxf(acc.x, 0.f); acc.y = fmaxf(acc.y, 0.f); }
    reinterpret_cast<float2*>(Hout + (size_t)node * D)[lane] = acc;
  }
}

// ---------------- launch ------------------------------------------------------
extern "C" void kernel_launch(void* const* d_in, const int* in_sizes, int n_in,
                              void* d_out, int out_size) {
  (void)in_sizes; (void)n_in; (void)out_size;
  const float* x  = (const float*)d_in[0];
  const int*   ei = (const int*)d_in[1];
  const int* src = ei;
  const int* dst = ei + EE;
  const float* W1 = (const float*)d_in[3];
  const float* b1 = (const float*)d_in[4];
  const float* W2 = (const float*)d_in[5];
  const float* b2 = (const float*)d_in[6];
  const float* W3 = (const float*)d_in[7];
  const float* b3 = (const float*)d_in[8];
  const float* W4 = (const float*)d_in[9];
  const float* b4 = (const float*)d_in[10];
  const float* Wl = (const float*)d_in[11];
  const float* bl = (const float*)d_in[12];
  float* out = (float*)d_out;

  float *buf0, *buf1;
  cudaGetSymbolAddress((void**)&buf0, g_buf0);
  cudaGetSymbolAddress((void**)&buf1, g_buf1);

  // ---- GCN normalization + CSR build (over dst, incl. self-loops) ----
  init_deg_kernel<<<(NN + 255) / 256, 256>>>();
  count_deg_kernel<<<(EE + 255) / 256, 256>>>(dst);
  block_sums_kernel<<<NSCAN_BLK, 256>>>();        // block sums + dinv
  scan_offsets_kernel<<<1, 64>>>();               // scan 40 block sums
  scan_write_kernel<<<NSCAN_BLK, 1024>>>();       // rowptr/cursor
  fill_csr_kernel<<<(NNZ + 255) / 256, 256>>>(src, dst);

  const int GEMM_BLOCKS = NN / 64;  // 625 (8 warps x 8 rows per block)
  const int AGG_BLOCKS = NN / 8;    // 5000 (8 warps per block)

  // L1: t = x @ W1 ; h1 = relu(agg(t) + b1)
  gemm_kernel<128, 64, false, false><<<dim3(GEMM_BLOCKS, 1), 256>>>(x, W1, nullptr, buf0);
  agg_kernel<64, true, true><<<AGG_BLOCKS, 256>>>(buf0, b1, buf1);
  // L2 (agg-first, d_in < d_out): a = agg(h1) ; h2 = relu(a @ W2 + b2)
  agg_kernel<64, false, false><<<AGG_BLOCKS, 256>>>(buf1, nullptr, buf0);
  gemm_kernel<64, 128, true, true><<<dim3(GEMM_BLOCKS, 2), 256>>>(buf0, W2, b2, buf1);
  // L3: t = h2 @ W3 ; h3 = relu(agg(t) + b3)
  gemm_kernel<128, 128, false, false><<<dim3(GEMM_BLOCKS, 2), 256>>>(buf1, W3, nullptr, buf0);
  agg_kernel<128, true, true><<<AGG_BLOCKS, 256>>>(buf0, b3, buf1);
  // L4: t = h3 @ W4 ; h4 = relu(agg(t) + b4)
  gemm_kernel<128, 64, false, false><<<dim3(GEMM_BLOCKS, 1), 256>>>(buf1, W4, nullptr, buf0);
  agg_kernel<64, true, true><<<AGG_BLOCKS, 256>>>(buf0, b4, buf1);
  // Head: out = h4 @ Wl + bl
  gemm_kernel<64, 32, false, true><<<dim3(GEMM_BLOCKS, 1), 256>>>(buf1, Wl, bl, out);
}